// round 15
// baseline (speedup 1.0000x reference)
#include <cuda_runtime.h>
#include <cuda_bf16.h>
#include <cstdint>

#define NN 50000
#define EE 800000
#define DD 128
#define LL 3
#define NB 196                        // scan blocks: ceil(50000/256)

// ---------------- device scratch ----------------
__device__ float g_Y1[NN * DD];
__device__ float g_Y2[NN * DD];
__device__ float g_Y3[NN * DD];
__device__ int   g_rowptr[NN + 1];
__device__ int   g_counts[NN];
__device__ int   g_bsum[NB];
__device__ int   g_boff[NB];
__device__ int   g_srcs  [EE];
__device__ int   g_src_in[EE];
__device__ int   g_dst_in[EE];
__device__ int   g_rank  [EE];
__device__ int   g_is32;
__device__ int   g_arrive;
__device__ volatile int g_release;
__device__ int   g_cnt1, g_cnt2;
__device__ volatile int g_go1, g_go2;
__device__ float g_degf[NN];
__device__ float g_adegf[NN];
// weight chains
__device__ float g_Q[4 * DD * DD];    // Q0=W1r@W2r Q1=W1r@W2o Q2=W1o@W2r Q3=W1o@W2o
__device__ float g_C[4 * DD * DD];    // C0..C3  [kb][k][n]
__device__ float g_c0[DD], g_c1[DD], g_c2[DD];
// combined transposed hi/lo weights: [n=128][k=512] bf16, packed 2/uint32
__device__ uint32_t g_B2h[DD * 256], g_B2l[DD * 256];

__device__ __forceinline__ uint32_t pack_bf2f(float a, float b) {
    __nv_bfloat16 ha = __float2bfloat16(a), hb = __float2bfloat16(b);
    uint16_t ua = *(uint16_t*)&ha, ub = *(uint16_t*)&hb;
    return (uint32_t)ua | ((uint32_t)ub << 16);
}
__device__ __forceinline__ uint32_t pack_lo2f(float a, float b) {
    float la = a - __bfloat162float(__float2bfloat16(a));
    float lb = b - __bfloat162float(__float2bfloat16(b));
    return pack_bf2f(la, lb);
}

// ---------------- init: counts + detect + sync reset -------------------------
__global__ void init_kernel(const unsigned int* __restrict__ w) {
    int i = blockIdx.x * blockDim.x + threadIdx.x;
    if (i == 0) {
        g_is32 = 0; g_arrive = 0; g_release = 0;
        g_cnt1 = 0; g_cnt2 = 0; g_go1 = 0; g_go2 = 0;
    }
    if (i < NN) g_counts[i] = 0;
    if (i < 4096) {
        unsigned int acc = 0;
        #pragma unroll
        for (int j = 0; j < 4; j++) acc |= w[2 * (i * 4 + j) + 1];
        if (acc) g_is32 = 1;
    }
}

// ---------------- weight chains (verified in R12: rel_err 4.4e-6) ------------
__device__ __forceinline__ void gsync(int* cnt, volatile int* go, int total) {
    __syncthreads();
    if (threadIdx.x == 0) {
        __threadfence();
        int tk = atomicAdd(cnt, 1);
        if (tk == total - 1) *go = 1;
        else while (*go == 0) { }
    }
    __syncthreads();
    __threadfence();
}

__global__ void wchain_kernel(const float* __restrict__ Wrel,
                              const float* __restrict__ Wroot,
                              const float* __restrict__ bias) {
    __shared__ float arow[DD];
    int b = blockIdx.x, t = threadIdx.x;   // 512 x 128

    // phase 1: Q_ab = W1a @ W2b
    {
        int ab = b >> 7, r = b & 127;
        const float* W1 = (ab < 2)        ? (Wrel + DD * DD)     : (Wroot + DD * DD);
        const float* W2 = ((ab & 1) == 0) ? (Wrel + 2 * DD * DD) : (Wroot + 2 * DD * DD);
        arow[t] = W1[r * DD + t];
        __syncthreads();
        float acc = 0.f;
        for (int k = 0; k < DD; k++) acc += arow[k] * W2[k * DD + t];
        g_Q[ab * DD * DD + r * DD + t] = acc;
    }
    gsync(&g_cnt1, &g_go1, 512);

    // phase 2: C_k rows + bias vectors
    {
        int ck = b >> 7, r = b & 127;
        const int nterms[4]  = {1, 3, 3, 1};
        const int arel[4][3] = {{0,0,0}, {1,0,0}, {1,1,0}, {1,0,0}};
        const int qi[4][3]   = {{3,0,0}, {3,1,2}, {1,2,0}, {0,0,0}};
        float acc = 0.f;
        for (int i = 0; i < nterms[ck]; i++) {
            const float* A0 = arel[ck][i] ? Wrel : Wroot;
            __syncthreads();
            arow[t] = A0[r * DD + t];
            __syncthreads();
            const float* Q = g_Q + qi[ck][i] * DD * DD;
            for (int k = 0; k < DD; k++) acc += arow[k] * Q[k * DD + t];
        }
        g_C[ck * DD * DD + r * DD + t] = acc;

        if (b == 0) {
            float s0 = 0.f, s1 = 0.f, s2 = 0.f;
            const float* W2r = Wrel  + 2 * DD * DD;
            const float* W2o = Wroot + 2 * DD * DD;
            for (int k = 0; k < DD; k++) {
                float b0 = bias[k], b1 = bias[DD + k];
                s0 += b0 * g_Q[3 * DD * DD + k * DD + t] + b1 * W2o[k * DD + t];
                s1 += b0 * (g_Q[1 * DD * DD + k * DD + t] + g_Q[2 * DD * DD + k * DD + t])
                    + b1 * W2r[k * DD + t];
                s2 += b0 * g_Q[0 * DD * DD + k * DD + t];
            }
            g_c0[t] = s0 + bias[2 * DD + t];
            g_c1[t] = s1;
            g_c2[t] = s2;
        }
    }
    gsync(&g_cnt2, &g_go2, 512);

    // phase 3: transpose+split C -> [n][512] hi/lo packed
    {
        int idx = b * 128 + t;
        if (idx < DD * 256) {
            int n = idx >> 8, kk = idx & 255;
            int k0 = kk * 2;
            int kb = k0 >> 7, kr = k0 & 127;
            float v0 = g_C[kb * DD * DD + kr * DD + n];
            float v1 = g_C[kb * DD * DD + (kr + 1) * DD + n];
            g_B2h[idx] = pack_bf2f(v0, v1);
            g_B2l[idx] = pack_lo2f(v0, v1);
        }
    }
}

// convert + histogram; atomic return value IS the edge's rank in its bucket
__global__ void convert_hist_kernel(const void* __restrict__ edges) {
    int e = blockIdx.x * blockDim.x + threadIdx.x;
    if (e >= EE) return;
    int s, d;
    if (g_is32) {
        const int* p = (const int*)edges;
        s = p[e]; d = p[EE + e];
    } else {
        const long long* p = (const long long*)edges;
        s = (int)p[e]; d = (int)p[EE + e];
    }
    g_src_in[e] = s;
    g_dst_in[e] = d;
    g_rank[e] = atomicAdd(&g_counts[d], 1);
}

// ---------------- single-kernel scan (also saves deg) ------------------------
__global__ void scan_kernel() {
    __shared__ int s[256];
    __shared__ int sel;
    int b = blockIdx.x, t = threadIdx.x;
    int i = b * 256 + t;
    int v = (i < NN) ? g_counts[i] : 0;
    s[t] = v;
    __syncthreads();
    #pragma unroll
    for (int o = 1; o < 256; o <<= 1) {
        int u = (t >= o) ? s[t - o] : 0;
        __syncthreads();
        s[t] += u;
        __syncthreads();
    }
    if (t == 255) {
        g_bsum[b] = s[255];
        __threadfence();
        int tk = atomicAdd(&g_arrive, 1);
        sel = (tk == NB - 1);
    }
    __syncthreads();
    if (sel) {
        __shared__ int m[256];
        int mv = (t < NB) ? g_bsum[t] : 0;
        m[t] = mv;
        __syncthreads();
        #pragma unroll
        for (int o = 1; o < 256; o <<= 1) {
            int u = (t >= o) ? m[t - o] : 0;
            __syncthreads();
            m[t] += u;
            __syncthreads();
        }
        if (t < NB) g_boff[t] = m[t] - mv;
        if (t == 255) g_rowptr[NN] = m[255];
        __threadfence();
        __syncthreads();
        if (t == 0) g_release = 1;
    } else if (t == 0) {
        while (g_release == 0) { }
    }
    __syncthreads();
    __threadfence();
    if (i < NN) {
        g_rowptr[i] = g_boff[b] + s[t] - v;
        g_degf[i]   = (float)v;
    }
}

// atomic-free scatter using precomputed ranks
__global__ void fill_kernel() {
    int e = blockIdx.x * blockDim.x + threadIdx.x;
    if (e >= EE) return;
    int d = g_dst_in[e];
    g_srcs[g_rowptr[d] + g_rank[e]] = g_src_in[e];
}

// ---------------- aggregation: warp per node, fp32 -> fp32 -------------------
// Pass 1 (do_adeg) also computes (A deg) on lane 0.
__global__ void agg_kernel(const float* __restrict__ x,
                           float* __restrict__ yout, int do_adeg) {
    int gw   = (blockIdx.x * blockDim.x + threadIdx.x) >> 5;
    int lane = threadIdx.x & 31;
    if (gw >= NN) return;
    int beg = g_rowptr[gw], end = g_rowptr[gw + 1];
    float4 acc = make_float4(0.f, 0.f, 0.f, 0.f);
    float sdeg = 0.f;
    const float* xb = x + lane * 4;
    int e = beg;
    for (; e + 3 < end; e += 4) {
        int s0 = g_srcs[e], s1 = g_srcs[e+1], s2 = g_srcs[e+2], s3 = g_srcs[e+3];
        float4 v0 = *(const float4*)(xb + (size_t)s0 * DD);
        float4 v1 = *(const float4*)(xb + (size_t)s1 * DD);
        float4 v2 = *(const float4*)(xb + (size_t)s2 * DD);
        float4 v3 = *(const float4*)(xb + (size_t)s3 * DD);
        acc.x += (v0.x + v1.x) + (v2.x + v3.x);
        acc.y += (v0.y + v1.y) + (v2.y + v3.y);
        acc.z += (v0.z + v1.z) + (v2.z + v3.z);
        acc.w += (v0.w + v1.w) + (v2.w + v3.w);
        if (do_adeg && lane == 0)
            sdeg += (g_degf[s0] + g_degf[s1]) + (g_degf[s2] + g_degf[s3]);
    }
    for (; e < end; e++) {
        int s = g_srcs[e];
        float4 v = *(const float4*)(xb + (size_t)s * DD);
        acc.x += v.x; acc.y += v.y; acc.z += v.z; acc.w += v.w;
        if (do_adeg && lane == 0) sdeg += g_degf[s];
    }
    *(float4*)(yout + (size_t)gw * DD + lane * 4) = acc;
    if (do_adeg && lane == 0) g_adegf[gw] = sdeg;
}

// ---------------- final GEMM: out = Sum_k Y_k @ C_k + c0 + deg c1 + adeg c2 --
// Virtual K=512 over {x, Y1, Y2, Y3}, fp32 in, split bf16 in-kernel.
// BM=128, BN=128, BK=32, 16 chunks, 256 threads, warp tile 64x32.

#define BK 32
#define ROWB 80
#define BUFB 40960
#define OFF_AH 0
#define OFF_AL 10240
#define OFF_BH 20480
#define OFF_BL 30720

__device__ __forceinline__ uint32_t smem_u32(const void* p) {
    uint32_t a;
    asm("{ .reg .u64 t; cvta.to.shared.u64 t, %1; cvt.u32.u64 %0, t; }" : "=r"(a) : "l"(p));
    return a;
}

#define LDSM4(r, a)                                                              \
    asm volatile("ldmatrix.sync.aligned.m8n8.x4.shared.b16 {%0,%1,%2,%3}, [%4];" \
        : "=r"((r)[0]), "=r"((r)[1]), "=r"((r)[2]), "=r"((r)[3]) : "r"(a))

__device__ __forceinline__ void mma16816(float* c, const uint32_t* a, const uint32_t* b) {
    asm volatile(
        "mma.sync.aligned.m16n8k16.row.col.f32.bf16.bf16.f32 "
        "{%0,%1,%2,%3}, {%4,%5,%6,%7}, {%8,%9}, {%0,%1,%2,%3};"
        : "+f"(c[0]), "+f"(c[1]), "+f"(c[2]), "+f"(c[3])
        : "r"(a[0]), "r"(a[1]), "r"(a[2]), "r"(a[3]), "r"(b[0]), "r"(b[1]));
}

__global__ void __launch_bounds__(256) gemm_final_kernel(
    const float* __restrict__ xin, float* __restrict__ out)
{
    extern __shared__ char smem[];
    int tid  = threadIdx.x;
    int wid  = tid >> 5;
    int lane = tid & 31;
    int g    = lane >> 2;
    int t    = lane & 3;
    int row0 = blockIdx.x * 128;
    int m0w  = (wid >> 2) * 64;
    int n0w  = (wid & 3) * 32;

    uint32_t sb = smem_u32(smem);
    uint32_t aoff_c = (uint32_t)(m0w + (lane & 15)) * ROWB + ((lane >> 4) << 4);
    uint32_t boff_c = (uint32_t)(n0w + ((lane >> 4) << 3) + (lane & 7)) * ROWB
                    + (((lane >> 3) & 1) << 4);

    float acc[4][4][4];
    #pragma unroll
    for (int i = 0; i < 4; i++)
        #pragma unroll
        for (int j = 0; j < 4; j++)
            #pragma unroll
            for (int q = 0; q < 4; q++) acc[i][j][q] = 0.f;

    float4   av[4];
    uint32_t bhv[8], blv[8];

    auto load_regs = [&](int c) {
        int kb = c >> 2;
        const float* src;
        if      (kb == 0) src = xin;
        else if (kb == 1) src = g_Y1;
        else if (kb == 2) src = g_Y2;
        else              src = g_Y3;
        int kc = (c & 3) * BK;
        #pragma unroll
        for (int j = 0; j < 4; j++) {
            int p = j * 256 + tid;
            int m = p >> 3;
            int kq = p & 7;
            int grow = row0 + m;
            av[j] = make_float4(0.f, 0.f, 0.f, 0.f);
            if (grow < NN)
                av[j] = *(const float4*)(src + (size_t)grow * DD + kc + 4 * kq);
        }
        #pragma unroll
        for (int j = 0; j < 8; j++) {
            int p = j * 256 + tid;
            int n = p >> 4;
            int kp = p & 15;
            int ui = n * 256 + c * 16 + kp;
            bhv[j] = g_B2h[ui];
            blv[j] = g_B2l[ui];
        }
    };

    auto store_smem = [&](int buf) {
        char* base = smem + buf * BUFB;
        #pragma unroll
        for (int j = 0; j < 4; j++) {
            int p = j * 256 + tid;
            int m = p >> 3;
            int kq = p & 7;
            float4 v = av[j];
            uint32_t off = (uint32_t)m * ROWB + 8 * kq;
            *(uint32_t*)(base + OFF_AH + off)     = pack_bf2f(v.x, v.y);
            *(uint32_t*)(base + OFF_AH + off + 4) = pack_bf2f(v.z, v.w);
            *(uint32_t*)(base + OFF_AL + off)     = pack_lo2f(v.x, v.y);
            *(uint32_t*)(base + OFF_AL + off + 4) = pack_lo2f(v.z, v.w);
        }
        #pragma unroll
        for (int j = 0; j < 8; j++) {
            int p = j * 256 + tid;
            int n = p >> 4;
            int kp = p & 15;
            uint32_t off = (uint32_t)n * ROWB + 4 * kp;
            *(uint32_t*)(base + OFF_BH + off) = bhv[j];
            *(uint32_t*)(base + OFF_BL + off) = blv[j];
        }
    };

    load_regs(0);
    store_smem(0);
    __syncthreads();

    #pragma unroll 1
    for (int c = 0; c < 16; c++) {
        if (c < 15) load_regs(c + 1);

        uint32_t bu = sb + (c & 1) * BUFB;
        #pragma unroll
        for (int s = 0; s < 2; s++) {
            uint32_t ks = s * 32;
            uint32_t ahq[4][4], alq[4][4], bhq[2][4], blq[2][4];
            #pragma unroll
            for (int mt = 0; mt < 4; mt++) {
                uint32_t adr = bu + OFF_AH + aoff_c + mt * (16 * ROWB) + ks;
                LDSM4(ahq[mt], adr);
                LDSM4(alq[mt], adr + (OFF_AL - OFF_AH));
            }
            #pragma unroll
            for (int p = 0; p < 2; p++) {
                uint32_t bdr = bu + OFF_BH + boff_c + p * (16 * ROWB) + ks;
                LDSM4(bhq[p], bdr);
                LDSM4(blq[p], bdr + (OFF_BL - OFF_BH));
            }
            #pragma unroll
            for (int mt = 0; mt < 4; mt++)
                #pragma unroll
                for (int p = 0; p < 2; p++) {
                    mma16816(acc[mt][2*p],   ahq[mt], &bhq[p][0]);
                    mma16816(acc[mt][2*p],   ahq[mt], &blq[p][0]);
                    mma16816(acc[mt][2*p],   alq[mt], &bhq[p][0]);
                    mma16816(acc[mt][2*p+1], ahq[mt], &bhq[p][2]);
                    mma16816(acc[mt][2*p+1], ahq[mt], &blq[p][2]);
                    mma16816(acc[mt][2*p+1], alq[mt], &bhq[p][2]);
                }
        }
        if (c < 15) {
            store_smem((c + 1) & 1);
            __syncthreads();
        }
    }

    // epilogue: out = acc + c0 + deg*c1 + (A deg)*c2
    #pragma unroll
    for (int nt = 0; nt < 4; nt++) {
        int col = n0w + nt * 8 + 2 * t;
        float cc00 = g_c0[col], cc01 = g_c0[col + 1];
        float cc10 = g_c1[col], cc11 = g_c1[col + 1];
        float cc20 = g_c2[col], cc21 = g_c2[col + 1];
        #pragma unroll
        for (int mt = 0; mt < 4; mt++) {
            int r = row0 + m0w + mt * 16 + g;
            if (r < NN) {
                float dr = g_degf[r], ar = g_adegf[r];
                float ox = acc[mt][nt][0] + cc00 + dr * cc10 + ar * cc20;
                float oy = acc[mt][nt][1] + cc01 + dr * cc11 + ar * cc21;
                *(float2*)(out + (size_t)r * DD + col) = make_float2(ox, oy);
            }
            if (r + 8 < NN) {
                float dr = g_degf[r + 8], ar = g_adegf[r + 8];
                float ox = acc[mt][nt][2] + cc00 + dr * cc10 + ar * cc20;
                float oy = acc[mt][nt][3] + cc01 + dr * cc11 + ar * cc21;
                *(float2*)(out + (size_t)(r + 8) * DD + col) = make_float2(ox, oy);
            }
        }
    }
}

// ---------------- launch ----------------
extern "C" void kernel_launch(void* const* d_in, const int* in_sizes, int n_in,
                              void* d_out, int out_size) {
    const float* x     = (const float*)d_in[0];
    const void*  edges = d_in[1];
    const float* Wrel  = (const float*)d_in[2];
    const float* Wroot = (const float*)d_in[3];
    const float* bias  = (const float*)d_in[4];
    float*       out   = (float*)d_out;

    float *y1, *y2, *y3;
    cudaGetSymbolAddress((void**)&y1, g_Y1);
    cudaGetSymbolAddress((void**)&y2, g_Y2);
    cudaGetSymbolAddress((void**)&y3, g_Y3);

    cudaFuncSetAttribute(gemm_final_kernel,
                         cudaFuncAttributeMaxDynamicSharedMemorySize, 2 * BUFB);

    const int T = 256;
    int gbE = (EE + T - 1) / T;

    init_kernel<<<NB, T>>>((const unsigned int*)edges);
    wchain_kernel<<<512, 128>>>(Wrel, Wroot, bias);
    convert_hist_kernel<<<gbE, T>>>(edges);
    scan_kernel<<<NB, 256>>>();
    fill_kernel<<<gbE, T>>>();

    int aggBlocks = (NN * 32 + T - 1) / T;
    agg_kernel<<<aggBlocks, T>>>(x,  y1, 1);   // Y1 = A x   (+ A deg)
    agg_kernel<<<aggBlocks, T>>>(y1, y2, 0);   // Y2 = A Y1
    agg_kernel<<<aggBlocks, T>>>(y2, y3, 0);   // Y3 = A Y2

    gemm_final_kernel<<<(NN + 127) / 128, T, 2 * BUFB>>>(x, out);
}

// round 16
// speedup vs baseline: 1.1138x; 1.1138x over previous
#include <cuda_runtime.h>
#include <cuda_bf16.h>
#include <cstdint>

#define NN 50000
#define EE 800000
#define DD 128
#define LL 3
#define NB 196                        // csr blocks
#define GT (NB * 256)                 // 50176 grid threads
#define EPT 16                        // edges per thread (16*50176 >= EE)
#define WPN (LL * 256 * DD)           // 98304 weight elements

// ---------------- device scratch ----------------
__device__ float g_buf0[NN * DD];
__device__ float g_buf1[NN * DD];
__device__ float g_agg [NN * DD];
__device__ int   g_rowptr[NN + 1];
__device__ int   g_counts[NN];
__device__ int   g_bsum[NB];
__device__ int   g_boff[NB];
__device__ int   g_srcs [EE];
__device__ int   g_is32;
__device__ int   g_cnt1, g_cnt2, g_cnt3;
__device__ volatile int g_go1, g_go2, g_go3;
// transposed bf16 weights: [layer][n=128][k=256] (k<128 -> Wrel, else Wroot)
__device__ unsigned short g_Bth[LL * DD * 2 * DD];
__device__ unsigned short g_Btl[LL * DD * 2 * DD];

// ---------------- init: counts + detect + weight prep + tickets --------------
__global__ void init_kernel(const unsigned int* __restrict__ w,
                            const float* __restrict__ Wrel,
                            const float* __restrict__ Wroot) {
    int i = blockIdx.x * blockDim.x + threadIdx.x;
    if (i == 0) {
        g_cnt1 = 0; g_cnt2 = 0; g_cnt3 = 0;
        g_go1 = 0; g_go2 = 0; g_go3 = 0;
        g_is32 = 0;
    }
    if (i < NN) g_counts[i] = 0;
    if (i < 4096) {
        unsigned int acc = 0;
        #pragma unroll
        for (int j = 0; j < 4; j++) acc |= w[2 * (i * 4 + j) + 1];
        if (acc) g_is32 = 1;
    }
    if (i < WPN) {
        int l = i / (256 * DD);
        int r = i - l * 256 * DD;
        int k = r / DD;
        int n = r - k * DD;
        float wv = (k < DD) ? Wrel[(size_t)l * DD * DD + k * DD + n]
                            : Wroot[(size_t)l * DD * DD + (k - DD) * DD + n];
        __nv_bfloat16 hi = __float2bfloat16(wv);
        float lo = wv - __bfloat162float(hi);
        __nv_bfloat16 lob = __float2bfloat16(lo);
        size_t o = (size_t)l * DD * 256 + (size_t)n * 256 + k;
        g_Bth[o] = *(unsigned short*)&hi;
        g_Btl[o] = *(unsigned short*)&lob;
    }
}

// ---------------- one-kernel CSR build ---------------------------------------
// 196 blocks, all co-resident (<=296 slots). Each thread owns EPT edges and
// keeps (src,dst,rank) in registers across phases -> no intermediate arrays.
__device__ __forceinline__ void gsync(int* cnt, volatile int* go) {
    __threadfence();
    __syncthreads();
    if (threadIdx.x == 0) {
        int tk = atomicAdd(cnt, 1);
        if (tk == NB - 1) *go = 1;
        else while (*go == 0) { }
    }
    __syncthreads();
    __threadfence();
}

__global__ void __launch_bounds__(256) csr_kernel(const void* __restrict__ edges) {
    int b = blockIdx.x, t = threadIdx.x;
    int gid = b * 256 + t;
    int ls[EPT], ld[EPT], lr[EPT];

    // ---- phase A: convert + histogram (rank = atomic return) ----
    int is32 = g_is32;
    #pragma unroll
    for (int j = 0; j < EPT; j++) {
        int e = gid + j * GT;
        ls[j] = -1;
        if (e < EE) {
            int s, d;
            if (is32) {
                const int* p = (const int*)edges;
                s = p[e]; d = p[EE + e];
            } else {
                const long long* p = (const long long*)edges;
                s = (int)p[e]; d = (int)p[EE + e];
            }
            ls[j] = s; ld[j] = d;
            lr[j] = atomicAdd(&g_counts[d], 1);
        }
    }
    gsync(&g_cnt1, &g_go1);

    // ---- phase B: exclusive scan of counts -> rowptr ----
    __shared__ int s[256];
    __shared__ int sel;
    int i = gid;
    int v = (i < NN) ? g_counts[i] : 0;
    s[t] = v;
    __syncthreads();
    #pragma unroll
    for (int o = 1; o < 256; o <<= 1) {
        int u = (t >= o) ? s[t - o] : 0;
        __syncthreads();
        s[t] += u;
        __syncthreads();
    }
    if (t == 255) {
        g_bsum[b] = s[255];
        __threadfence();
        int tk = atomicAdd(&g_cnt2, 1);
        sel = (tk == NB - 1);
    }
    __syncthreads();
    if (sel) {
        __shared__ int m[256];
        int mv = (t < NB) ? g_bsum[t] : 0;
        m[t] = mv;
        __syncthreads();
        #pragma unroll
        for (int o = 1; o < 256; o <<= 1) {
            int u = (t >= o) ? m[t - o] : 0;
            __syncthreads();
            m[t] += u;
            __syncthreads();
        }
        if (t < NB) g_boff[t] = m[t] - mv;
        if (t == 255) g_rowptr[NN] = m[255];
        __threadfence();
        __syncthreads();
        if (t == 0) g_go2 = 1;
    } else if (t == 0) {
        while (g_go2 == 0) { }
    }
    __syncthreads();
    __threadfence();
    if (i < NN) g_rowptr[i] = g_boff[b] + s[t] - v;

    // ---- phase C: all rowptr visible, then register-resident scatter ----
    gsync(&g_cnt3, &g_go3);
    #pragma unroll
    for (int j = 0; j < EPT; j++) {
        if (ls[j] >= 0)
            g_srcs[g_rowptr[ld[j]] + lr[j]] = ls[j];
    }
}

// ---------------- aggregation: one warp per destination node ----------------
__global__ void agg_kernel(const float* __restrict__ x) {
    int gw   = (blockIdx.x * blockDim.x + threadIdx.x) >> 5;
    int lane = threadIdx.x & 31;
    if (gw >= NN) return;
    int beg = g_rowptr[gw], end = g_rowptr[gw + 1];
    float4 acc = make_float4(0.f, 0.f, 0.f, 0.f);
    const float* xb = x + lane * 4;
    int e = beg;
    for (; e + 3 < end; e += 4) {
        int s0 = g_srcs[e], s1 = g_srcs[e+1], s2 = g_srcs[e+2], s3 = g_srcs[e+3];
        float4 v0 = *(const float4*)(xb + (size_t)s0 * DD);
        float4 v1 = *(const float4*)(xb + (size_t)s1 * DD);
        float4 v2 = *(const float4*)(xb + (size_t)s2 * DD);
        float4 v3 = *(const float4*)(xb + (size_t)s3 * DD);
        acc.x += (v0.x + v1.x) + (v2.x + v3.x);
        acc.y += (v0.y + v1.y) + (v2.y + v3.y);
        acc.z += (v0.z + v1.z) + (v2.z + v3.z);
        acc.w += (v0.w + v1.w) + (v2.w + v3.w);
    }
    for (; e < end; e++) {
        float4 v = *(const float4*)(xb + (size_t)g_srcs[e] * DD);
        acc.x += v.x; acc.y += v.y; acc.z += v.z; acc.w += v.w;
    }
    *(float4*)(g_agg + (size_t)gw * DD + lane * 4) = acc;
}

// ---------------- fused tensor-core GEMM via mma.sync + ldmatrix -------------
// out[m][n] = sum_k A[m][k] W[k][n] + bias[n];  A = [agg | x]  (virtual K=256).
// Split bf16: acc += Ahi*Bhi + Ahi*Blo + Alo*Bhi.
// BM=128, BN=128, BK=32, 256 threads = 8 warps, warp tile 64x32.
// ROWB=80 padding -> conflict-free LDSM.

#define BK 32
#define ROWB 80
#define BUFB 40960
#define OFF_AH 0
#define OFF_AL 10240
#define OFF_BH 20480
#define OFF_BL 30720

__device__ __forceinline__ uint32_t smem_u32(const void* p) {
    uint32_t a;
    asm("{ .reg .u64 t; cvta.to.shared.u64 t, %1; cvt.u32.u64 %0, t; }" : "=r"(a) : "l"(p));
    return a;
}

#define LDSM4(r, a)                                                              \
    asm volatile("ldmatrix.sync.aligned.m8n8.x4.shared.b16 {%0,%1,%2,%3}, [%4];" \
        : "=r"((r)[0]), "=r"((r)[1]), "=r"((r)[2]), "=r"((r)[3]) : "r"(a))

__device__ __forceinline__ void mma16816(float* c, const uint32_t* a, const uint32_t* b) {
    asm volatile(
        "mma.sync.aligned.m16n8k16.row.col.f32.bf16.bf16.f32 "
        "{%0,%1,%2,%3}, {%4,%5,%6,%7}, {%8,%9}, {%0,%1,%2,%3};"
        : "+f"(c[0]), "+f"(c[1]), "+f"(c[2]), "+f"(c[3])
        : "r"(a[0]), "r"(a[1]), "r"(a[2]), "r"(a[3]), "r"(b[0]), "r"(b[1]));
}

__device__ __forceinline__ uint32_t pack_bf2f(float a, float b) {
    __nv_bfloat16 ha = __float2bfloat16(a), hb = __float2bfloat16(b);
    uint16_t ua = *(uint16_t*)&ha, ub = *(uint16_t*)&hb;
    return (uint32_t)ua | ((uint32_t)ub << 16);
}

__global__ void __launch_bounds__(256) gemm_mma_kernel(
    const float* __restrict__ xin,
    int layer,
    const float* __restrict__ bias,
    float* __restrict__ out)
{
    extern __shared__ char smem[];
    int tid  = threadIdx.x;
    int wid  = tid >> 5;
    int lane = tid & 31;
    int g    = lane >> 2;
    int t    = lane & 3;
    int row0 = blockIdx.x * 128;
    int m0w  = (wid >> 2) * 64;
    int n0w  = (wid & 3) * 32;

    uint32_t sb = smem_u32(smem);
    uint32_t aoff_c = (uint32_t)(m0w + (lane & 15)) * ROWB + ((lane >> 4) << 4);
    uint32_t boff_c = (uint32_t)(n0w + ((lane >> 4) << 3) + (lane & 7)) * ROWB
                    + (((lane >> 3) & 1) << 4);

    const uint32_t* Bth = (const uint32_t*)(g_Bth + (size_t)layer * DD * 256);
    const uint32_t* Btl = (const uint32_t*)(g_Btl + (size_t)layer * DD * 256);

    float acc[4][4][4];
    #pragma unroll
    for (int i = 0; i < 4; i++)
        #pragma unroll
        for (int j = 0; j < 4; j++)
            #pragma unroll
            for (int q = 0; q < 4; q++) acc[i][j][q] = 0.f;

    float4   av[4];
    uint32_t bhv[8], blv[8];

    auto load_regs = [&](int c) {
        int kv0 = c * BK;
        const float* src = (kv0 < DD) ? g_agg : xin;
        int kc = kv0 & 127;
        #pragma unroll
        for (int j = 0; j < 4; j++) {
            int p = j * 256 + tid;
            int m = p >> 3;
            int kq = p & 7;
            int grow = row0 + m;
            av[j] = make_float4(0.f, 0.f, 0.f, 0.f);
            if (grow < NN)
                av[j] = *(const float4*)(src + (size_t)grow * DD + kc + 4 * kq);
        }
        #pragma unroll
        for (int j = 0; j < 8; j++) {
            int p = j * 256 + tid;
            int n = p >> 4;
            int kp = p & 15;
            int ui = n * 128 + c * 16 + kp;
            bhv[j] = Bth[ui];
            blv[j] = Btl[ui];
        }
    };

    auto store_smem = [&](int buf) {
        char* base = smem + buf * BUFB;
        #pragma unroll
        for (int j = 0; j < 4; j++) {
            int p = j * 256 + tid;
            int m = p >> 3;
            int kq = p & 7;
            float4 v = av[j];
            float lx = v.x - __bfloat162float(__float2bfloat16(v.x));
            float ly = v.y - __bfloat162float(__float2bfloat16(v.y));
            float lz = v.z - __bfloat162float(__float2bfloat16(v.z));
            float lw = v.w - __bfloat162float(__float2bfloat16(v.w));
            uint32_t off = (uint32_t)m * ROWB + 8 * kq;
            *(uint32_t*)(base + OFF_AH + off)     = pack_bf2f(v.x, v.y);
            *(uint32_t*)(base + OFF_AH + off + 4) = pack_bf2f(v.z, v.w);
            *(uint32_t*)(base + OFF_AL + off)     = pack_bf2f(lx, ly);
            *(uint32_t*)(base + OFF_AL + off + 4) = pack_bf2f(lz, lw);
        }
        #pragma unroll
        for (int j = 0; j < 8; j++) {
            int p = j * 256 + tid;
            int n = p >> 4;
            int kp = p & 15;
            uint32_t off = (uint32_t)n * ROWB + 4 * kp;
            *(uint32_t*)(base + OFF_BH + off) = bhv[j];
            *(uint32_t*)(base + OFF_BL + off) = blv[j];
        }
    };

    load_regs(0);
    store_smem(0);
    __syncthreads();

    #pragma unroll 1
    for (int c = 0; c < 8; c++) {
        if (c < 7) load_regs(c + 1);

        uint32_t bu = sb + (c & 1) * BUFB;
        #pragma unroll
        for (int s = 0; s < 2; s++) {
            uint32_t ks = s * 32;
            uint32_t ahq[4][4], alq[4][4], bhq[2][4], blq[2][4];
            #pragma unroll
            for (int mt = 0; mt < 4; mt++) {
                uint32_t adr = bu + OFF_AH + aoff_c + mt * (16 * ROWB) + ks;
                LDSM4(ahq[mt], adr);
                LDSM4(alq[mt], adr + (OFF_AL - OFF_AH));
            }
            #pragma unroll
            for (int p = 0; p < 2; p++) {
                uint32_t bdr = bu + OFF_BH + boff_c + p * (16 * ROWB) + ks;
                LDSM4(bhq[p], bdr);
                LDSM4(blq[p], bdr + (OFF_BL - OFF_BH));
            }
            #pragma unroll
            for (int mt = 0; mt < 4; mt++)
                #pragma unroll
                for (int p = 0; p < 2; p++) {
                    mma16816(acc[mt][2*p],   ahq[mt], &bhq[p][0]);
                    mma16816(acc[mt][2*p],   ahq[mt], &blq[p][0]);
                    mma16816(acc[mt][2*p],   alq[mt], &bhq[p][0]);
                    mma16816(acc[mt][2*p+1], ahq[mt], &bhq[p][2]);
                    mma16816(acc[mt][2*p+1], ahq[mt], &blq[p][2]);
                    mma16816(acc[mt][2*p+1], alq[mt], &bhq[p][2]);
                }
        }
        if (c < 7) {
            store_smem((c + 1) & 1);
            __syncthreads();
        }
    }

    #pragma unroll
    for (int nt = 0; nt < 4; nt++) {
        int col = n0w + nt * 8 + 2 * t;
        float b0 = bias[col], b1 = bias[col + 1];
        #pragma unroll
        for (int mt = 0; mt < 4; mt++) {
            int r = row0 + m0w + mt * 16 + g;
            if (r < NN) {
                float2 o0 = make_float2(acc[mt][nt][0] + b0, acc[mt][nt][1] + b1);
                *(float2*)(out + (size_t)r * DD + col) = o0;
            }
            if (r + 8 < NN) {
                float2 o1 = make_float2(acc[mt][nt][2] + b0, acc[mt][nt][3] + b1);
                *(float2*)(out + (size_t)(r + 8) * DD + col) = o1;
            }
        }
    }
}

// ---------------- launch ----------------
extern "C" void kernel_launch(void* const* d_in, const int* in_sizes, int n_in,
                              void* d_out, int out_size) {
    const float* x     = (const float*)d_in[0];
    const void*  edges = d_in[1];
    const float* Wrel  = (const float*)d_in[2];
    const float* Wroot = (const float*)d_in[3];
    const float* bias  = (const float*)d_in[4];
    float*       out   = (float*)d_out;

    float *buf0, *buf1;
    cudaGetSymbolAddress((void**)&buf0, g_buf0);
    cudaGetSymbolAddress((void**)&buf1, g_buf1);

    cudaFuncSetAttribute(gemm_mma_kernel,
                         cudaFuncAttributeMaxDynamicSharedMemorySize, 2 * BUFB);

    const int T = 256;

    init_kernel<<<WPN / T, T>>>((const unsigned int*)edges, Wrel, Wroot);
    csr_kernel<<<NB, T>>>(edges);

    int aggBlocks  = (NN * 32 + T - 1) / T;
    int gemmBlocks = (NN + 127) / 128;   // 391

    const float* cur = x;
    float* outs[LL] = { buf0, buf1, out };
    for (int l = 0; l < LL; l++) {
        agg_kernel<<<aggBlocks, T>>>(cur);
        gemm_mma_kernel<<<gemmBlocks, T, 2 * BUFB>>>(cur, l, bias + (size_t)l * DD,
                                                     outs[l]);
        cur = outs[l];
    }
}

// round 17
// speedup vs baseline: 1.1768x; 1.0566x over previous
#include <cuda_runtime.h>
#include <cuda_bf16.h>
#include <cstdint>

#define NN 50000
#define EE 800000
#define DD 128
#define LL 3
#define NB 196                        // scan blocks: ceil(50000/256)
#define WPN (LL * 256 * DD)           // 98304 weight elements

// ---------------- device scratch ----------------
__device__ float g_buf0[NN * DD];
__device__ float g_buf1[NN * DD];
__device__ float g_agg [NN * DD];
__device__ int   g_rowptr[NN + 1];
__device__ int   g_counts[NN];
__device__ int   g_bsum[NB];
__device__ int   g_boff[NB];
__device__ int   g_srcs  [EE];
__device__ int   g_src_in[EE];
__device__ int   g_dst_in[EE];
__device__ int   g_rank  [EE];
__device__ int   g_is32;
__device__ int   g_arrive;
__device__ volatile int g_release;
// transposed bf16 weights: [layer][n=128][k=256] (k<128 -> Wrel, else Wroot)
__device__ unsigned short g_Bth[LL * DD * 2 * DD];
__device__ unsigned short g_Btl[LL * DD * 2 * DD];

// ---------------- init: counts + detect + weight prep ------------------------
__global__ void init_kernel(const unsigned int* __restrict__ w,
                            const float* __restrict__ Wrel,
                            const float* __restrict__ Wroot) {
    int i = blockIdx.x * blockDim.x + threadIdx.x;
    if (i == 0) { g_is32 = 0; g_arrive = 0; g_release = 0; }
    if (i < NN) g_counts[i] = 0;
    if (i < 4096) {
        unsigned int acc = 0;
        #pragma unroll
        for (int j = 0; j < 4; j++) acc |= w[2 * (i * 4 + j) + 1];
        if (acc) g_is32 = 1;
    }
    if (i < WPN) {
        int l = i / (256 * DD);
        int r = i - l * 256 * DD;
        int k = r / DD;
        int n = r - k * DD;
        float wv = (k < DD) ? Wrel[(size_t)l * DD * DD + k * DD + n]
                            : Wroot[(size_t)l * DD * DD + (k - DD) * DD + n];
        __nv_bfloat16 hi = __float2bfloat16(wv);
        float lo = wv - __bfloat162float(hi);
        __nv_bfloat16 lob = __float2bfloat16(lo);
        size_t o = (size_t)l * DD * 256 + (size_t)n * 256 + k;
        g_Bth[o] = *(unsigned short*)&hi;
        g_Btl[o] = *(unsigned short*)&lob;
    }
}

// convert + histogram; atomic return value IS the edge's rank in its bucket
__global__ void convert_hist_kernel(const void* __restrict__ edges) {
    int e = blockIdx.x * blockDim.x + threadIdx.x;
    if (e >= EE) return;
    int s, d;
    if (g_is32) {
        const int* p = (const int*)edges;
        s = p[e]; d = p[EE + e];
    } else {
        const long long* p = (const long long*)edges;
        s = (int)p[e]; d = (int)p[EE + e];
    }
    g_src_in[e] = s;
    g_dst_in[e] = d;
    g_rank[e] = atomicAdd(&g_counts[d], 1);
}

// ---------------- single-kernel scan (grid-sync via atomic ticket) -----------
__global__ void scan_kernel() {
    __shared__ int s[256];
    __shared__ int sel;
    int b = blockIdx.x, t = threadIdx.x;
    int i = b * 256 + t;
    int v = (i < NN) ? g_counts[i] : 0;
    s[t] = v;
    __syncthreads();
    #pragma unroll
    for (int o = 1; o < 256; o <<= 1) {
        int u = (t >= o) ? s[t - o] : 0;
        __syncthreads();
        s[t] += u;
        __syncthreads();
    }
    if (t == 255) {
        g_bsum[b] = s[255];
        __threadfence();
        int tk = atomicAdd(&g_arrive, 1);
        sel = (tk == NB - 1);
    }
    __syncthreads();
    if (sel) {
        __shared__ int m[256];
        int mv = (t < NB) ? g_bsum[t] : 0;
        m[t] = mv;
        __syncthreads();
        #pragma unroll
        for (int o = 1; o < 256; o <<= 1) {
            int u = (t >= o) ? m[t - o] : 0;
            __syncthreads();
            m[t] += u;
            __syncthreads();
        }
        if (t < NB) g_boff[t] = m[t] - mv;
        if (t == 255) g_rowptr[NN] = m[255];
        __threadfence();
        __syncthreads();
        if (t == 0) g_release = 1;
    } else if (t == 0) {
        while (g_release == 0) { }
    }
    __syncthreads();
    __threadfence();
    if (i < NN) {
        g_rowptr[i] = g_boff[b] + s[t] - v;
    }
}

// atomic-free scatter using precomputed ranks
__global__ void fill_kernel() {
    int e = blockIdx.x * blockDim.x + threadIdx.x;
    if (e >= EE) return;
    int d = g_dst_in[e];
    g_srcs[g_rowptr[d] + g_rank[e]] = g_src_in[e];
}

// ---------------- aggregation: one warp per destination node ----------------
__global__ void agg_kernel(const float* __restrict__ x) {
    int gw   = (blockIdx.x * blockDim.x + threadIdx.x) >> 5;
    int lane = threadIdx.x & 31;
    if (gw >= NN) return;
    int beg = g_rowptr[gw], end = g_rowptr[gw + 1];
    float4 acc = make_float4(0.f, 0.f, 0.f, 0.f);
    const float* xb = x + lane * 4;
    int e = beg;
    for (; e + 3 < end; e += 4) {
        int s0 = g_srcs[e], s1 = g_srcs[e+1], s2 = g_srcs[e+2], s3 = g_srcs[e+3];
        float4 v0 = *(const float4*)(xb + (size_t)s0 * DD);
        float4 v1 = *(const float4*)(xb + (size_t)s1 * DD);
        float4 v2 = *(const float4*)(xb + (size_t)s2 * DD);
        float4 v3 = *(const float4*)(xb + (size_t)s3 * DD);
        acc.x += (v0.x + v1.x) + (v2.x + v3.x);
        acc.y += (v0.y + v1.y) + (v2.y + v3.y);
        acc.z += (v0.z + v1.z) + (v2.z + v3.z);
        acc.w += (v0.w + v1.w) + (v2.w + v3.w);
    }
    for (; e < end; e++) {
        float4 v = *(const float4*)(xb + (size_t)g_srcs[e] * DD);
        acc.x += v.x; acc.y += v.y; acc.z += v.z; acc.w += v.w;
    }
    *(float4*)(g_agg + (size_t)gw * DD + lane * 4) = acc;
}

// ---------------- GEMM: cp.async B + reg-staged A + ldmatrix + mma.sync ------
// out[m][n] = sum_k A[m][k] W[k][n] + bias[n];  A = [agg | x]  (virtual K=256).
// Split bf16: acc += Ahi*Bhi + Ahi*Blo + Alo*Bhi.
// BM=128, BN=128, BK=32, 256 threads, warp tile 64x32, target 2 CTAs/SM.
// B planes cp.async'd straight from pre-split global (no regs); A converted
// in-kernel (staged across compute for latency hiding).

#define BK 32
#define ROWB 80
#define BUFB 40960
#define OFF_AH 0
#define OFF_AL 10240
#define OFF_BH 20480
#define OFF_BL 30720

__device__ __forceinline__ uint32_t smem_u32(const void* p) {
    uint32_t a;
    asm("{ .reg .u64 t; cvta.to.shared.u64 t, %1; cvt.u32.u64 %0, t; }" : "=r"(a) : "l"(p));
    return a;
}

#define LDSM4(r, a)                                                              \
    asm volatile("ldmatrix.sync.aligned.m8n8.x4.shared.b16 {%0,%1,%2,%3}, [%4];" \
        : "=r"((r)[0]), "=r"((r)[1]), "=r"((r)[2]), "=r"((r)[3]) : "r"(a))

__device__ __forceinline__ void mma16816(float* c, const uint32_t* a, const uint32_t* b) {
    asm volatile(
        "mma.sync.aligned.m16n8k16.row.col.f32.bf16.bf16.f32 "
        "{%0,%1,%2,%3}, {%4,%5,%6,%7}, {%8,%9}, {%0,%1,%2,%3};"
        : "+f"(c[0]), "+f"(c[1]), "+f"(c[2]), "+f"(c[3])
        : "r"(a[0]), "r"(a[1]), "r"(a[2]), "r"(a[3]), "r"(b[0]), "r"(b[1]));
}

__device__ __forceinline__ uint32_t pack_bf2f(float a, float b) {
    __nv_bfloat16 ha = __float2bfloat16(a), hb = __float2bfloat16(b);
    uint16_t ua = *(uint16_t*)&ha, ub = *(uint16_t*)&hb;
    return (uint32_t)ua | ((uint32_t)ub << 16);
}

__global__ void __launch_bounds__(256, 2) gemm_mma_kernel(
    const float* __restrict__ xin,
    int layer,
    const float* __restrict__ bias,
    float* __restrict__ out)
{
    extern __shared__ char smem[];
    int tid  = threadIdx.x;
    int wid  = tid >> 5;
    int lane = tid & 31;
    int g    = lane >> 2;
    int t    = lane & 3;
    int row0 = blockIdx.x * 128;
    int m0w  = (wid >> 2) * 64;
    int n0w  = (wid & 3) * 32;

    uint32_t sb = smem_u32(smem);
    uint32_t aoff_c = (uint32_t)(m0w + (lane & 15)) * ROWB + ((lane >> 4) << 4);
    uint32_t boff_c = (uint32_t)(n0w + ((lane >> 4) << 3) + (lane & 7)) * ROWB
                    + (((lane >> 3) & 1) << 4);

    const uint32_t* Bth = (const uint32_t*)(g_Bth + (size_t)layer * DD * 256);
    const uint32_t* Btl = (const uint32_t*)(g_Btl + (size_t)layer * DD * 256);

    float acc[4][4][4];
    #pragma unroll
    for (int i = 0; i < 4; i++)
        #pragma unroll
        for (int j = 0; j < 4; j++)
            #pragma unroll
            for (int q = 0; q < 4; q++) acc[i][j][q] = 0.f;

    float4 av[4];

    // cp.async both B planes for chunk c into buffer buf (4 x 16B per thread)
    auto issue_B = [&](int c, int buf) {
        uint32_t base = sb + buf * BUFB;
        #pragma unroll
        for (int j = 0; j < 4; j++) {
            int idx = j * 256 + tid;            // 0..1023
            int plane = idx >> 9;               // 0: BH  1: BL
            int r = (idx & 511) >> 2;           // 0..127
            int q = idx & 3;                    // 16B quarter
            uint32_t dst = base + OFF_BH + plane * (OFF_BL - OFF_BH)
                         + (uint32_t)r * ROWB + q * 16;
            const uint32_t* src = (plane ? Btl : Bth) + r * 128 + c * 16 + q * 4;
            asm volatile("cp.async.cg.shared.global [%0], [%1], 16;"
                         :: "r"(dst), "l"(src));
        }
        asm volatile("cp.async.commit_group;");
    };

    auto load_A_regs = [&](int c) {
        int kv0 = c * BK;
        const float* src = (kv0 < DD) ? g_agg : xin;
        int kc = kv0 & 127;
        #pragma unroll
        for (int j = 0; j < 4; j++) {
            int p = j * 256 + tid;
            int m = p >> 3;
            int kq = p & 7;
            int grow = row0 + m;
            av[j] = make_float4(0.f, 0.f, 0.f, 0.f);
            if (grow < NN)
                av[j] = *(const float4*)(src + (size_t)grow * DD + kc + 4 * kq);
        }
    };

    auto store_A = [&](int buf) {
        char* base = smem + buf * BUFB;
        #pragma unroll
        for (int j = 0; j < 4; j++) {
            int p = j * 256 + tid;
            int m = p >> 3;
            int kq = p & 7;
            float4 v = av[j];
            float lx = v.x - __bfloat162float(__float2bfloat16(v.x));
            float ly = v.y - __bfloat162float(__float2bfloat16(v.y));
            float lz = v.z - __bfloat162float(__float2bfloat16(v.z));
            float lw = v.w - __bfloat162float(__float2bfloat16(v.w));
            uint32_t off = (uint32_t)m * ROWB + 8 * kq;
            *(uint32_t*)(base + OFF_AH + off)     = pack_bf2f(v.x, v.y);
            *(uint32_t*)(base + OFF_AH + off + 4) = pack_bf2f(v.z, v.w);
            *(uint32_t*)(base + OFF_AL + off)     = pack_bf2f(lx, ly);
            *(uint32_t*)(base + OFF_AL + off + 4) = pack_bf2f(lz, lw);
        }
    };

    // prologue: chunk 0
    issue_B(0, 0);
    load_A_regs(0);
    store_A(0);
    asm volatile("cp.async.wait_group 0;");
    __syncthreads();

    #pragma unroll 1
    for (int c = 0; c < 8; c++) {
        // buffer (c+1)&1 is free: its readers passed the previous sync
        if (c < 7) {
            issue_B(c + 1, (c + 1) & 1);
            load_A_regs(c + 1);
        }

        uint32_t bu = sb + (c & 1) * BUFB;
        #pragma unroll
        for (int s = 0; s < 2; s++) {
            uint32_t ks = s * 32;
            uint32_t ahq[4][4], alq[4][4], bhq[2][4], blq[2][4];
            #pragma unroll
            for (int mt = 0; mt < 4; mt++) {
                uint32_t adr = bu + OFF_AH + aoff_c + mt * (16 * ROWB) + ks;
                LDSM4(ahq[mt], adr);
                LDSM4(alq[mt], adr + (OFF_AL - OFF_AH));
            }
            #pragma unroll
            for (int p = 0; p < 2; p++) {
                uint32_t bdr = bu + OFF_BH + boff_c + p * (16 * ROWB) + ks;
                LDSM4(bhq[p], bdr);
                LDSM4(blq[p], bdr + (OFF_BL - OFF_BH));
            }
            #pragma unroll
            for (int mt = 0; mt < 4; mt++)
                #pragma unroll
                for (int p = 0; p < 2; p++) {
                    mma16816(acc[mt][2*p],   ahq[mt], &bhq[p][0]);
                    mma16816(acc[mt][2*p],   ahq[mt], &blq[p][0]);
                    mma16816(acc[mt][2*p],   alq[mt], &bhq[p][0]);
                    mma16816(acc[mt][2*p+1], ahq[mt], &bhq[p][2]);
                    mma16816(acc[mt][2*p+1], ahq[mt], &blq[p][2]);
                    mma16816(acc[mt][2*p+1], alq[mt], &bhq[p][2]);
                }
        }
        if (c < 7) {
            store_A((c + 1) & 1);
            asm volatile("cp.async.wait_group 0;");
            __syncthreads();
        }
    }

    #pragma unroll
    for (int nt = 0; nt < 4; nt++) {
        int col = n0w + nt * 8 + 2 * t;
        float b0 = bias[col], b1 = bias[col + 1];
        #pragma unroll
        for (int mt = 0; mt < 4; mt++) {
            int r = row0 + m0w + mt * 16 + g;
            if (r < NN) {
                float2 o0 = make_float2(acc[mt][nt][0] + b0, acc[mt][nt][1] + b1);
                *(float2*)(out + (size_t)r * DD + col) = o0;
            }
            if (r + 8 < NN) {
                float2 o1 = make_float2(acc[mt][nt][2] + b0, acc[mt][nt][3] + b1);
                *(float2*)(out + (size_t)(r + 8) * DD + col) = o1;
            }
        }
    }
}

// ---------------- launch ----------------
extern "C" void kernel_launch(void* const* d_in, const int* in_sizes, int n_in,
                              void* d_out, int out_size) {
    const float* x     = (const float*)d_in[0];
    const void*  edges = d_in[1];
    const float* Wrel  = (const float*)d_in[2];
    const float* Wroot = (const float*)d_in[3];
    const float* bias  = (const float*)d_in[4];
    float*       out   = (float*)d_out;

    float *buf0, *buf1;
    cudaGetSymbolAddress((void**)&buf0, g_buf0);
    cudaGetSymbolAddress((void**)&buf1, g_buf1);

    cudaFuncSetAttribute(gemm_mma_kernel,
                         cudaFuncAttributeMaxDynamicSharedMemorySize, 2 * BUFB);

    const int T = 256;
    int gbE = (EE + T - 1) / T;

    init_kernel<<<WPN / T, T>>>((const unsigned int*)edges, Wrel, Wroot);
    convert_hist_kernel<<<gbE, T>>>(edges);
    scan_kernel<<<NB, 256>>>();
    fill_kernel<<<gbE, T>>>();

    int aggBlocks  = (NN * 32 + T - 1) / T;
    int gemmBlocks = (NN + 127) / 128;   // 391

    const float* cur = x;
    float* outs[LL] = { buf0, buf1, out };
    for (int l = 0; l < LL; l++) {
        agg_kernel<<<aggBlocks, T>>>(cur);
        gemm_mma_kernel<<<gemmBlocks, T, 2 * BUFB>>>(cur, l, bias + (size_t)l * DD,
                                                     outs[l]);
        cur = outs[l];
    }
}